// round 8
// baseline (speedup 1.0000x reference)
#include <cuda_runtime.h>
#include <cstdint>

#define BB 8
#define NN 2048
#define FF 128
#define UU 128

// ---------------- scratch (__device__ globals; no allocs allowed) ----------
__device__ float g_T[BB * NN * UU];   // 8 MB: T = X@Wf + bf, tf32-rounded
__device__ float g_e[BB * NN];        // e_j = exp(a_j), tf32-rounded
__device__ float g_Wfr[FF * UU];      // Wf tf32-rounded
__device__ float g_v[FF];             // v = Wf @ w1
__device__ float g_b0[1];             // b0 = bf . w1

// ---------------- helpers ---------------------------------------------------
__device__ __forceinline__ unsigned tf32_bits(float x) {
    unsigned r; asm("cvt.rna.tf32.f32 %0, %1;" : "=r"(r) : "f"(x)); return r;
}
__device__ __forceinline__ float tf32_round(float x) {
    return __uint_as_float(tf32_bits(x));
}
__device__ __forceinline__ void cp16(void* smem, const void* gmem) {
    unsigned s = (unsigned)__cvta_generic_to_shared(smem);
    asm volatile("cp.async.cg.shared.global [%0], [%1], 16;" :: "r"(s), "l"(gmem));
}
__device__ __forceinline__ void cp_commit() { asm volatile("cp.async.commit_group;"); }
template <int N> __device__ __forceinline__ void cp_wait() {
    asm volatile("cp.async.wait_group %0;" :: "n"(N));
}

#define MMA_TF32(c, a0, a1, a2, a3, b0, b1)                                    \
    asm volatile(                                                              \
        "mma.sync.aligned.m16n8k8.row.col.f32.tf32.tf32.f32 "                  \
        "{%0,%1,%2,%3}, {%4,%5,%6,%7}, {%8,%9}, {%0,%1,%2,%3};"                \
        : "+f"((c)[0]), "+f"((c)[1]), "+f"((c)[2]), "+f"((c)[3])               \
        : "r"(a0), "r"(a1), "r"(a2), "r"(a3), "r"(b0), "r"(b1))

// ---------------------------------------------------------------------------
// k_wf: pre-round Wf to tf32.
// ---------------------------------------------------------------------------
__global__ void k_wf(const float* __restrict__ Wf, float* __restrict__ Wfr) {
    const int i = blockIdx.x * blockDim.x + threadIdx.x;
    if (i < FF * UU) Wfr[i] = tf32_round(Wf[i]);
}

// ---------------------------------------------------------------------------
// k_wv: v[f] = sum_u Wf[f][u]*w1[u]  (blocks 0..127);  block 128: b0 = bf.w1
// ---------------------------------------------------------------------------
__global__ void __launch_bounds__(128) k_wv(const float* __restrict__ Wf,
                                            const float* __restrict__ bf,
                                            const float* __restrict__ Ws,
                                            float* __restrict__ v,
                                            float* __restrict__ b0) {
    __shared__ float red[4];
    const int f = blockIdx.x, u = threadIdx.x;
    float t;
    if (f < FF) t = Wf[f * UU + u] * Ws[u];
    else        t = bf[u] * Ws[u];
    #pragma unroll
    for (int o = 16; o; o >>= 1) t += __shfl_xor_sync(0xFFFFFFFFu, t, o);
    if ((u & 31) == 0) red[u >> 5] = t;
    __syncthreads();
    if (u == 0) {
        float s = red[0] + red[1] + red[2] + red[3];
        if (f < FF) v[f] = s; else b0[0] = s;
    }
}

// ---------------------------------------------------------------------------
// k_ae: e_j = tf32_round( exp( X_j . v + b0 ) ).  One warp per row.
// (softmax shift-invariance: max subtraction cancels; |a| <= ~3 so exp safe)
// ---------------------------------------------------------------------------
__global__ void __launch_bounds__(256) k_ae(const float* __restrict__ X,
                                            const float* __restrict__ v,
                                            const float* __restrict__ b0,
                                            float* __restrict__ e) {
    const int gw = (blockIdx.x * blockDim.x + threadIdx.x) >> 5;
    const int lane = threadIdx.x & 31;
    if (gw >= BB * NN) return;
    const float4 x = ((const float4*)(X + (long)gw * FF))[lane];
    const float4 w = ((const float4*)v)[lane];
    float s = x.x * w.x + x.y * w.y + x.z * w.z + x.w * w.w;
    #pragma unroll
    for (int o = 16; o; o >>= 1) s += __shfl_xor_sync(0xFFFFFFFFu, s, o);
    if (lane == 0) e[gw] = tf32_round(expf(s + b0[0]));
}

// ---------------------------------------------------------------------------
// k_feat: T = tf32_round( X @ Wfr + bf )  (tf32 mma GEMM) — R4's passing one.
// ---------------------------------------------------------------------------
struct FeatSmem {
    float xs[2][128][36];
    float ds[2][32][136];
};
#define FEAT_SMEM_BYTES sizeof(FeatSmem)

__global__ void __launch_bounds__(256) k_feat(const float* __restrict__ X,
                                              const float* __restrict__ Wfr,
                                              const float* __restrict__ bf,
                                              float* __restrict__ T) {
    extern __shared__ char smem_raw[];
    FeatSmem& sm = *reinterpret_cast<FeatSmem*>(smem_raw);

    const long i0 = (long)blockIdx.x * 128;
    const int tid = threadIdx.x;
    const int lane = tid & 31;
    const int w = tid >> 5;
    const int wr = w >> 1, wc = w & 1;
    const int tg = lane & 3, gid = lane >> 2;

    float c[2][8][4];
    #pragma unroll
    for (int mt = 0; mt < 2; mt++)
        #pragma unroll
        for (int nt = 0; nt < 8; nt++)
            #pragma unroll
            for (int q = 0; q < 4; q++) c[mt][nt][q] = 0.f;

    auto issue_tile = [&](int t) {
        const int bufi = t & 1;
        const int k0 = t * 32;
        #pragma unroll
        for (int q = 0; q < 4; q++) {
            const int idx = tid + q * 256;
            const int i = idx >> 3, q4 = idx & 7;
            cp16(&sm.xs[bufi][i][q4 * 4], X + (i0 + i) * FF + k0 + q4 * 4);
        }
        #pragma unroll
        for (int q = 0; q < 4; q++) {
            const int idx = tid + q * 256;
            const int kk = idx >> 5, u4 = idx & 31;
            cp16(&sm.ds[bufi][kk][u4 * 4], Wfr + (long)(k0 + kk) * UU + u4 * 4);
        }
        cp_commit();
    };

    issue_tile(0);
    for (int t = 0; t < 4; t++) {
        const int cur = t & 1;
        if (t + 1 < 4) { issue_tile(t + 1); cp_wait<1>(); }
        else           { cp_wait<0>(); }
        __syncthreads();

        const float (*xs)[36] = sm.xs[cur];
        const float (*Ds)[136] = sm.ds[cur];

        #pragma unroll
        for (int s = 0; s < 4; s++) {
            const int kA0 = s * 8 + tg;
            unsigned av[2][4];
            #pragma unroll
            for (int mt = 0; mt < 2; mt++) {
                const int ri = wr * 32 + mt * 16 + gid;
                av[mt][0] = tf32_bits(xs[ri][kA0]);
                av[mt][1] = tf32_bits(xs[ri + 8][kA0]);
                av[mt][2] = tf32_bits(xs[ri][kA0 + 4]);
                av[mt][3] = tf32_bits(xs[ri + 8][kA0 + 4]);
            }
            #pragma unroll
            for (int nt = 0; nt < 8; nt++) {
                const int ncol = wc * 64 + nt * 8 + gid;
                const unsigned b0r = __float_as_uint(Ds[s * 8 + tg][ncol]);
                const unsigned b1r = __float_as_uint(Ds[s * 8 + tg + 4][ncol]);
                #pragma unroll
                for (int mt = 0; mt < 2; mt++)
                    MMA_TF32(c[mt][nt], av[mt][0], av[mt][1], av[mt][2], av[mt][3],
                             b0r, b1r);
            }
        }
        __syncthreads();
    }

    #pragma unroll
    for (int mt = 0; mt < 2; mt++) {
        const int rloc0 = wr * 32 + mt * 16 + gid;
        #pragma unroll
        for (int half = 0; half < 2; half++) {
            const int rloc = rloc0 + half * 8;
            float* orow = T + (i0 + rloc) * UU;
            #pragma unroll
            for (int nt = 0; nt < 8; nt++) {
                const int col = wc * 64 + nt * 8 + tg * 2;
                float2 v;
                v.x = tf32_round(c[mt][nt][half * 2 + 0] + bf[col]);
                v.y = tf32_round(c[mt][nt][half * 2 + 1] + bf[col + 1]);
                *(float2*)(orow + col) = v;
            }
        }
    }
}

// ---------------------------------------------------------------------------
// k_attn: out[b,i,:] = (sum_j m_ij e_j T_j) / (sum_j m_ij e_j)
// 512 threads, 16 warps (4x4 warp grid, warp tile 32x32), 64 k-tiles of 32.
// A side = register bitmasks (adjacency packed per tile) -> zero A smem frags.
// B side = cp.async 4-deep ring of T tiles [32][128] (tf32, pad 136).
// ---------------------------------------------------------------------------
struct AttnSmem {
    int   adjs[4][128][36];    // raw adjacency ring (row pad 144B)
    float Bs[4][32][136];      // T tile ring (pad 136: conflict-free frags)
    float es[NN];              // e[b] staged once (tf32 values)
    unsigned maskw[128];       // per-tile packed adjacency words
    float den[128];
};
#define ATTN_SMEM_BYTES sizeof(AttnSmem)

__global__ void __launch_bounds__(512) k_attn(const int* __restrict__ adj,
                                              const float* __restrict__ Tm,
                                              const float* __restrict__ e,
                                              float* __restrict__ out) {
    extern __shared__ char smem_raw[];
    AttnSmem& sm = *reinterpret_cast<AttnSmem*>(smem_raw);

    const int b = blockIdx.y;
    const long i0 = (long)blockIdx.x * 128;
    const int tid = threadIdx.x;
    const int lane = tid & 31;
    const int w = tid >> 5;
    const int wr = w & 3;            // warp row  -> rows [wr*32, +32)
    const int wc = w >> 2;           // warp col  -> cols [wc*32, +32)
    const int tg = lane & 3;
    const int gid = lane >> 2;

    // builder mapping: thread -> (row, k-quarter)
    const int brow = tid >> 2;
    const int bq = tid & 3;

    const int* adjBase = adj + ((long)b * NN + i0) * NN;
    const float* Tb = Tm + (long)b * NN * UU;
    const float* eb = e + (long)b * NN;

    // stage e[b] (8 KB) once
    ((float4*)sm.es)[tid] = ((const float4*)eb)[tid];

    float c[2][4][4];
    #pragma unroll
    for (int mt = 0; mt < 2; mt++)
        #pragma unroll
        for (int nt = 0; nt < 4; nt++)
            #pragma unroll
            for (int q = 0; q < 4; q++) c[mt][nt][q] = 0.f;

    float den_acc = 0.f;

    auto issue_tile = [&](int t) {
        const int st = t & 3;
        const int k0 = t * 32;
        #pragma unroll
        for (int q = 0; q < 2; q++) {
            const int idx = tid + q * 512;           // 0..1023
            const int r = idx >> 3, ch = idx & 7;
            cp16(&sm.adjs[st][r][ch * 4], adjBase + (long)r * NN + k0 + ch * 4);
        }
        #pragma unroll
        for (int q = 0; q < 2; q++) {
            const int idx = tid + q * 512;
            const int kk = idx >> 5, u4 = idx & 31;
            cp16(&sm.Bs[st][kk][u4 * 4], Tb + (long)(k0 + kk) * UU + u4 * 4);
        }
        cp_commit();
    };

    issue_tile(0); issue_tile(1); issue_tile(2);

    for (int t = 0; t < 64; t++) {
        const int st = t & 3;
        const int k0 = t * 32;

        if (t <= 61)      cp_wait<2>();
        else if (t == 62) cp_wait<1>();
        else              cp_wait<0>();
        __syncthreads();   // tile t staged; prev tile's mask/B reads complete

        if (t + 3 < 64) issue_tile(t + 3);

        // ---- pack adjacency tile into 128 bitmask words + denominators ----
        {
            const int* ar = &sm.adjs[st][brow][bq * 8];
            const int4 m0 = *(const int4*)ar;
            const int4 m1 = *(const int4*)(ar + 4);
            unsigned bits = (unsigned)(m0.x != 0)        | ((unsigned)(m0.y != 0) << 1)
                          | ((unsigned)(m0.z != 0) << 2) | ((unsigned)(m0.w != 0) << 3)
                          | ((unsigned)(m1.x != 0) << 4) | ((unsigned)(m1.y != 0) << 5)
                          | ((unsigned)(m1.z != 0) << 6) | ((unsigned)(m1.w != 0) << 7);
            unsigned word = bits << (bq * 8);
            word |= __shfl_xor_sync(0xFFFFFFFFu, word, 1);
            word |= __shfl_xor_sync(0xFFFFFFFFu, word, 2);

            const float4 e0 = *(const float4*)&sm.es[k0 + bq * 8];
            const float4 e1 = *(const float4*)&sm.es[k0 + bq * 8 + 4];
            float d = (m0.x ? e0.x : 0.f) + (m0.y ? e0.y : 0.f)
                    + (m0.z ? e0.z : 0.f) + (m0.w ? e0.w : 0.f)
                    + (m1.x ? e1.x : 0.f) + (m1.y ? e1.y : 0.f)
                    + (m1.z ? e1.z : 0.f) + (m1.w ? e1.w : 0.f);
            d += __shfl_xor_sync(0xFFFFFFFFu, d, 1);
            d += __shfl_xor_sync(0xFFFFFFFFu, d, 2);
            if (bq == 0) { sm.maskw[brow] = word; den_acc += d; }
        }
        __syncthreads();   // masks ready

        // ---- mma: A from bitmask registers, B frags from smem ----
        const unsigned w0 = sm.maskw[wr * 32 + gid];
        const unsigned w1 = sm.maskw[wr * 32 + gid + 8];
        const unsigned w2 = sm.maskw[wr * 32 + gid + 16];
        const unsigned w3 = sm.maskw[wr * 32 + gid + 24];
        const float (*Bsl)[136] = sm.Bs[st];

        #pragma unroll
        for (int s = 0; s < 4; s++) {
            const int kk = s * 8 + tg;
            const unsigned e0 = __float_as_uint(sm.es[k0 + kk]);
            const unsigned e1 = __float_as_uint(sm.es[k0 + kk + 4]);
            const unsigned a00 = ((w0 >> kk) & 1u)       ? e0 : 0u;
            const unsigned a01 = ((w1 >> kk) & 1u)       ? e0 : 0u;
            const unsigned a02 = ((w0 >> (kk + 4)) & 1u) ? e1 : 0u;
            const unsigned a03 = ((w1 >> (kk + 4)) & 1u) ? e1 : 0u;
            const unsigned a10 = ((w2 >> kk) & 1u)       ? e0 : 0u;
            const unsigned a11 = ((w3 >> kk) & 1u)       ? e0 : 0u;
            const unsigned a12 = ((w2 >> (kk + 4)) & 1u) ? e1 : 0u;
            const unsigned a13 = ((w3 >> (kk + 4)) & 1u) ? e1 : 0u;
            #pragma unroll
            for (int nt = 0; nt < 4; nt++) {
                const int ncol = wc * 32 + nt * 8 + gid;
                const unsigned b0r = __float_as_uint(Bsl[kk][ncol]);
                const unsigned b1r = __float_as_uint(Bsl[kk + 4][ncol]);
                MMA_TF32(c[0][nt], a00, a01, a02, a03, b0r, b1r);
                MMA_TF32(c[1][nt], a10, a11, a12, a13, b0r, b1r);
            }
        }
    }

    // publish denominators
    if (bq == 0) sm.den[brow] = den_acc;
    __syncthreads();

    // epilogue
    #pragma unroll
    for (int mt = 0; mt < 2; mt++) {
        #pragma unroll
        for (int half = 0; half < 2; half++) {
            const int rloc = wr * 32 + mt * 16 + gid + half * 8;
            float dn = sm.den[rloc];
            dn = (dn != 0.f) ? dn : 1.f;
            const float inv = 1.f / dn;
            float* orow = out + ((long)b * NN + i0 + rloc) * UU;
            #pragma unroll
            for (int nt = 0; nt < 4; nt++) {
                const int col = wc * 32 + nt * 8 + tg * 2;
                float2 v;
                v.x = c[mt][nt][half * 2 + 0] * inv;
                v.y = c[mt][nt][half * 2 + 1] * inv;
                *(float2*)(orow + col) = v;
            }
        }
    }
}

// ---------------------------------------------------------------------------
extern "C" void kernel_launch(void* const* d_in, const int* in_sizes, int n_in,
                              void* d_out, int out_size) {
    const float* X   = (const float*)d_in[0];  // [B,N,F]
    const int*   adj = (const int*)  d_in[1];  // [B,N,N]
    const float* Wf  = (const float*)d_in[2];  // [F,U]
    const float* bf  = (const float*)d_in[3];  // [U]
    const float* Ws  = (const float*)d_in[4];  // [2U]
    // d_in[5] = bs: constant along softmax axis -> cancels. w2 likewise unused.
    float* out = (float*)d_out;

    float *T, *e, *Wfr, *v, *b0;
    cudaGetSymbolAddress((void**)&T, g_T);
    cudaGetSymbolAddress((void**)&e, g_e);
    cudaGetSymbolAddress((void**)&Wfr, g_Wfr);
    cudaGetSymbolAddress((void**)&v, g_v);
    cudaGetSymbolAddress((void**)&b0, g_b0);

    cudaFuncSetAttribute(k_feat, cudaFuncAttributeMaxDynamicSharedMemorySize,
                         (int)FEAT_SMEM_BYTES);
    cudaFuncSetAttribute(k_attn, cudaFuncAttributeMaxDynamicSharedMemorySize,
                         (int)ATTN_SMEM_BYTES);

    k_wf<<<(FF * UU + 255) / 256, 256>>>(Wf, Wfr);
    k_wv<<<129, 128>>>(Wf, bf, Ws, v, b0);
    k_feat<<<128, 256, FEAT_SMEM_BYTES>>>(X, Wfr, bf, T);
    k_ae<<<2048, 256>>>(X, v, b0, e);
    dim3 grid(16, BB);
    k_attn<<<grid, 512, ATTN_SMEM_BYTES>>>(adj, T, e, out);
}

// round 9
// speedup vs baseline: 1.0179x; 1.0179x over previous
#include <cuda_runtime.h>
#include <cstdint>

#define BB 8
#define NN 2048
#define FF 128
#define UU 128

// ---------------- scratch (__device__ globals; no allocs allowed) ----------
__device__ float g_T[BB * NN * UU];   // 8 MB: T = X@Wf + bf, tf32-rounded
__device__ float g_e[BB * NN];        // e_j = exp(a_j), tf32-rounded
__device__ float g_Wfr[FF * UU];      // Wf tf32-rounded
__device__ float g_v[FF];             // v = Wf @ w1
__device__ float g_b0[1];             // b0 = bf . w1

// ---------------- helpers ---------------------------------------------------
__device__ __forceinline__ unsigned tf32_bits(float x) {
    unsigned r; asm("cvt.rna.tf32.f32 %0, %1;" : "=r"(r) : "f"(x)); return r;
}
__device__ __forceinline__ float tf32_round(float x) {
    return __uint_as_float(tf32_bits(x));
}
__device__ __forceinline__ void cp16(void* smem, const void* gmem) {
    unsigned s = (unsigned)__cvta_generic_to_shared(smem);
    asm volatile("cp.async.cg.shared.global [%0], [%1], 16;" :: "r"(s), "l"(gmem));
}
__device__ __forceinline__ void cp_commit() { asm volatile("cp.async.commit_group;"); }
template <int N> __device__ __forceinline__ void cp_wait() {
    asm volatile("cp.async.wait_group %0;" :: "n"(N));
}

#define MMA_TF32(c, a0, a1, a2, a3, b0, b1)                                    \
    asm volatile(                                                              \
        "mma.sync.aligned.m16n8k8.row.col.f32.tf32.tf32.f32 "                  \
        "{%0,%1,%2,%3}, {%4,%5,%6,%7}, {%8,%9}, {%0,%1,%2,%3};"                \
        : "+f"((c)[0]), "+f"((c)[1]), "+f"((c)[2]), "+f"((c)[3])               \
        : "r"(a0), "r"(a1), "r"(a2), "r"(a3), "r"(b0), "r"(b1))

// ---------------------------------------------------------------------------
// k_wf: pre-round Wf to tf32.
// ---------------------------------------------------------------------------
__global__ void k_wf(const float* __restrict__ Wf, float* __restrict__ Wfr) {
    const int i = blockIdx.x * blockDim.x + threadIdx.x;
    if (i < FF * UU) Wfr[i] = tf32_round(Wf[i]);
}

// ---------------------------------------------------------------------------
// k_wv: v[f] = sum_u Wf[f][u]*w1[u]  (blocks 0..127);  block 128: b0 = bf.w1
// ---------------------------------------------------------------------------
__global__ void __launch_bounds__(128) k_wv(const float* __restrict__ Wf,
                                            const float* __restrict__ bf,
                                            const float* __restrict__ Ws,
                                            float* __restrict__ v,
                                            float* __restrict__ b0) {
    __shared__ float red[4];
    const int f = blockIdx.x, u = threadIdx.x;
    float t;
    if (f < FF) t = Wf[f * UU + u] * Ws[u];
    else        t = bf[u] * Ws[u];
    #pragma unroll
    for (int o = 16; o; o >>= 1) t += __shfl_xor_sync(0xFFFFFFFFu, t, o);
    if ((u & 31) == 0) red[u >> 5] = t;
    __syncthreads();
    if (u == 0) {
        float s = red[0] + red[1] + red[2] + red[3];
        if (f < FF) v[f] = s; else b0[0] = s;
    }
}

// ---------------------------------------------------------------------------
// k_ae: e_j = tf32_round( exp( X_j . v + b0 ) ).  One warp per row.
// (softmax shift-invariance: max subtraction cancels; |a| <= ~3 so exp safe)
// ---------------------------------------------------------------------------
__global__ void __launch_bounds__(256) k_ae(const float* __restrict__ X,
                                            const float* __restrict__ v,
                                            const float* __restrict__ b0,
                                            float* __restrict__ e) {
    const int gw = (blockIdx.x * blockDim.x + threadIdx.x) >> 5;
    const int lane = threadIdx.x & 31;
    if (gw >= BB * NN) return;
    const float4 x = ((const float4*)(X + (long)gw * FF))[lane];
    const float4 w = ((const float4*)v)[lane];
    float s = x.x * w.x + x.y * w.y + x.z * w.z + x.w * w.w;
    #pragma unroll
    for (int o = 16; o; o >>= 1) s += __shfl_xor_sync(0xFFFFFFFFu, s, o);
    if (lane == 0) e[gw] = tf32_round(expf(s + b0[0]));
}

// ---------------------------------------------------------------------------
// k_feat: T = tf32_round( X @ Wfr + bf )  (tf32 mma GEMM) — R4's passing one.
// ---------------------------------------------------------------------------
struct FeatSmem {
    float xs[2][128][36];
    float ds[2][32][136];
};
#define FEAT_SMEM_BYTES sizeof(FeatSmem)

__global__ void __launch_bounds__(256) k_feat(const float* __restrict__ X,
                                              const float* __restrict__ Wfr,
                                              const float* __restrict__ bf,
                                              float* __restrict__ T) {
    extern __shared__ char smem_raw[];
    FeatSmem& sm = *reinterpret_cast<FeatSmem*>(smem_raw);

    const long i0 = (long)blockIdx.x * 128;
    const int tid = threadIdx.x;
    const int lane = tid & 31;
    const int w = tid >> 5;
    const int wr = w >> 1, wc = w & 1;
    const int tg = lane & 3, gid = lane >> 2;

    float c[2][8][4];
    #pragma unroll
    for (int mt = 0; mt < 2; mt++)
        #pragma unroll
        for (int nt = 0; nt < 8; nt++)
            #pragma unroll
            for (int q = 0; q < 4; q++) c[mt][nt][q] = 0.f;

    auto issue_tile = [&](int t) {
        const int bufi = t & 1;
        const int k0 = t * 32;
        #pragma unroll
        for (int q = 0; q < 4; q++) {
            const int idx = tid + q * 256;
            const int i = idx >> 3, q4 = idx & 7;
            cp16(&sm.xs[bufi][i][q4 * 4], X + (i0 + i) * FF + k0 + q4 * 4);
        }
        #pragma unroll
        for (int q = 0; q < 4; q++) {
            const int idx = tid + q * 256;
            const int kk = idx >> 5, u4 = idx & 31;
            cp16(&sm.ds[bufi][kk][u4 * 4], Wfr + (long)(k0 + kk) * UU + u4 * 4);
        }
        cp_commit();
    };

    issue_tile(0);
    for (int t = 0; t < 4; t++) {
        const int cur = t & 1;
        if (t + 1 < 4) { issue_tile(t + 1); cp_wait<1>(); }
        else           { cp_wait<0>(); }
        __syncthreads();

        const float (*xs)[36] = sm.xs[cur];
        const float (*Ds)[136] = sm.ds[cur];

        #pragma unroll
        for (int s = 0; s < 4; s++) {
            const int kA0 = s * 8 + tg;
            unsigned av[2][4];
            #pragma unroll
            for (int mt = 0; mt < 2; mt++) {
                const int ri = wr * 32 + mt * 16 + gid;
                av[mt][0] = tf32_bits(xs[ri][kA0]);
                av[mt][1] = tf32_bits(xs[ri + 8][kA0]);
                av[mt][2] = tf32_bits(xs[ri][kA0 + 4]);
                av[mt][3] = tf32_bits(xs[ri + 8][kA0 + 4]);
            }
            #pragma unroll
            for (int nt = 0; nt < 8; nt++) {
                const int ncol = wc * 64 + nt * 8 + gid;
                const unsigned b0r = __float_as_uint(Ds[s * 8 + tg][ncol]);
                const unsigned b1r = __float_as_uint(Ds[s * 8 + tg + 4][ncol]);
                #pragma unroll
                for (int mt = 0; mt < 2; mt++)
                    MMA_TF32(c[mt][nt], av[mt][0], av[mt][1], av[mt][2], av[mt][3],
                             b0r, b1r);
            }
        }
        __syncthreads();
    }

    #pragma unroll
    for (int mt = 0; mt < 2; mt++) {
        const int rloc0 = wr * 32 + mt * 16 + gid;
        #pragma unroll
        for (int half = 0; half < 2; half++) {
            const int rloc = rloc0 + half * 8;
            float* orow = T + (i0 + rloc) * UU;
            #pragma unroll
            for (int nt = 0; nt < 8; nt++) {
                const int col = wc * 64 + nt * 8 + tg * 2;
                float2 v;
                v.x = tf32_round(c[mt][nt][half * 2 + 0] + bf[col]);
                v.y = tf32_round(c[mt][nt][half * 2 + 1] + bf[col + 1]);
                *(float2*)(orow + col) = v;
            }
        }
    }
}

// ---------------------------------------------------------------------------
// k_attn: out[b,i,:] = (sum_j m_ij e_j T_j) / (sum_j m_ij e_j)
// 512 threads, 16 warps (4x4 warp grid, warp tile 32x32), 64 k-tiles of 32.
// A side = register bitmasks (adjacency packed per tile) -> zero A smem frags.
// B side = cp.async 4-deep ring of T tiles [32][128] (tf32, pad 136).
// ---------------------------------------------------------------------------
struct AttnSmem {
    int   adjs[4][128][36];    // raw adjacency ring (row pad 144B)
    float Bs[4][32][136];      // T tile ring (pad 136: conflict-free frags)
    float es[NN];              // e[b] staged once (tf32 values)
    unsigned maskw[128];       // per-tile packed adjacency words
    float den[128];
};
#define ATTN_SMEM_BYTES sizeof(AttnSmem)

__global__ void __launch_bounds__(512) k_attn(const int* __restrict__ adj,
                                              const float* __restrict__ Tm,
                                              const float* __restrict__ e,
                                              float* __restrict__ out) {
    extern __shared__ char smem_raw[];
    AttnSmem& sm = *reinterpret_cast<AttnSmem*>(smem_raw);

    const int b = blockIdx.y;
    const long i0 = (long)blockIdx.x * 128;
    const int tid = threadIdx.x;
    const int lane = tid & 31;
    const int w = tid >> 5;
    const int wr = w & 3;            // warp row  -> rows [wr*32, +32)
    const int wc = w >> 2;           // warp col  -> cols [wc*32, +32)
    const int tg = lane & 3;
    const int gid = lane >> 2;

    // builder mapping: thread -> (row, k-quarter)
    const int brow = tid >> 2;
    const int bq = tid & 3;

    const int* adjBase = adj + ((long)b * NN + i0) * NN;
    const float* Tb = Tm + (long)b * NN * UU;
    const float* eb = e + (long)b * NN;

    // stage e[b] (8 KB) once
    ((float4*)sm.es)[tid] = ((const float4*)eb)[tid];

    float c[2][4][4];
    #pragma unroll
    for (int mt = 0; mt < 2; mt++)
        #pragma unroll
        for (int nt = 0; nt < 4; nt++)
            #pragma unroll
            for (int q = 0; q < 4; q++) c[mt][nt][q] = 0.f;

    float den_acc = 0.f;

    auto issue_tile = [&](int t) {
        const int st = t & 3;
        const int k0 = t * 32;
        #pragma unroll
        for (int q = 0; q < 2; q++) {
            const int idx = tid + q * 512;           // 0..1023
            const int r = idx >> 3, ch = idx & 7;
            cp16(&sm.adjs[st][r][ch * 4], adjBase + (long)r * NN + k0 + ch * 4);
        }
        #pragma unroll
        for (int q = 0; q < 2; q++) {
            const int idx = tid + q * 512;
            const int kk = idx >> 5, u4 = idx & 31;
            cp16(&sm.Bs[st][kk][u4 * 4], Tb + (long)(k0 + kk) * UU + u4 * 4);
        }
        cp_commit();
    };

    issue_tile(0); issue_tile(1); issue_tile(2);

    for (int t = 0; t < 64; t++) {
        const int st = t & 3;
        const int k0 = t * 32;

        if (t <= 61)      cp_wait<2>();
        else if (t == 62) cp_wait<1>();
        else              cp_wait<0>();
        __syncthreads();   // tile t staged; prev tile's mask/B reads complete

        if (t + 3 < 64) issue_tile(t + 3);

        // ---- pack adjacency tile into 128 bitmask words + denominators ----
        {
            const int* ar = &sm.adjs[st][brow][bq * 8];
            const int4 m0 = *(const int4*)ar;
            const int4 m1 = *(const int4*)(ar + 4);
            unsigned bits = (unsigned)(m0.x != 0)        | ((unsigned)(m0.y != 0) << 1)
                          | ((unsigned)(m0.z != 0) << 2) | ((unsigned)(m0.w != 0) << 3)
                          | ((unsigned)(m1.x != 0) << 4) | ((unsigned)(m1.y != 0) << 5)
                          | ((unsigned)(m1.z != 0) << 6) | ((unsigned)(m1.w != 0) << 7);
            unsigned word = bits << (bq * 8);
            word |= __shfl_xor_sync(0xFFFFFFFFu, word, 1);
            word |= __shfl_xor_sync(0xFFFFFFFFu, word, 2);

            const float4 e0 = *(const float4*)&sm.es[k0 + bq * 8];
            const float4 e1 = *(const float4*)&sm.es[k0 + bq * 8 + 4];
            float d = (m0.x ? e0.x : 0.f) + (m0.y ? e0.y : 0.f)
                    + (m0.z ? e0.z : 0.f) + (m0.w ? e0.w : 0.f)
                    + (m1.x ? e1.x : 0.f) + (m1.y ? e1.y : 0.f)
                    + (m1.z ? e1.z : 0.f) + (m1.w ? e1.w : 0.f);
            d += __shfl_xor_sync(0xFFFFFFFFu, d, 1);
            d += __shfl_xor_sync(0xFFFFFFFFu, d, 2);
            if (bq == 0) { sm.maskw[brow] = word; den_acc += d; }
        }
        __syncthreads();   // masks ready

        // ---- mma: A from bitmask registers, B frags from smem ----
        const unsigned w0 = sm.maskw[wr * 32 + gid];
        const unsigned w1 = sm.maskw[wr * 32 + gid + 8];
        const unsigned w2 = sm.maskw[wr * 32 + gid + 16];
        const unsigned w3 = sm.maskw[wr * 32 + gid + 24];
        const float (*Bsl)[136] = sm.Bs[st];

        #pragma unroll
        for (int s = 0; s < 4; s++) {
            const int kk = s * 8 + tg;
            const unsigned e0 = __float_as_uint(sm.es[k0 + kk]);
            const unsigned e1 = __float_as_uint(sm.es[k0 + kk + 4]);
            const unsigned a00 = ((w0 >> kk) & 1u)       ? e0 : 0u;
            const unsigned a01 = ((w1 >> kk) & 1u)       ? e0 : 0u;
            const unsigned a02 = ((w0 >> (kk + 4)) & 1u) ? e1 : 0u;
            const unsigned a03 = ((w1 >> (kk + 4)) & 1u) ? e1 : 0u;
            const unsigned a10 = ((w2 >> kk) & 1u)       ? e0 : 0u;
            const unsigned a11 = ((w3 >> kk) & 1u)       ? e0 : 0u;
            const unsigned a12 = ((w2 >> (kk + 4)) & 1u) ? e1 : 0u;
            const unsigned a13 = ((w3 >> (kk + 4)) & 1u) ? e1 : 0u;
            #pragma unroll
            for (int nt = 0; nt < 4; nt++) {
                const int ncol = wc * 32 + nt * 8 + gid;
                const unsigned b0r = __float_as_uint(Bsl[kk][ncol]);
                const unsigned b1r = __float_as_uint(Bsl[kk + 4][ncol]);
                MMA_TF32(c[0][nt], a00, a01, a02, a03, b0r, b1r);
                MMA_TF32(c[1][nt], a10, a11, a12, a13, b0r, b1r);
            }
        }
    }

    // publish denominators
    if (bq == 0) sm.den[brow] = den_acc;
    __syncthreads();

    // epilogue
    #pragma unroll
    for (int mt = 0; mt < 2; mt++) {
        #pragma unroll
        for (int half = 0; half < 2; half++) {
            const int rloc = wr * 32 + mt * 16 + gid + half * 8;
            float dn = sm.den[rloc];
            dn = (dn != 0.f) ? dn : 1.f;
            const float inv = 1.f / dn;
            float* orow = out + ((long)b * NN + i0 + rloc) * UU;
            #pragma unroll
            for (int nt = 0; nt < 4; nt++) {
                const int col = wc * 32 + nt * 8 + tg * 2;
                float2 v;
                v.x = c[mt][nt][half * 2 + 0] * inv;
                v.y = c[mt][nt][half * 2 + 1] * inv;
                *(float2*)(orow + col) = v;
            }
        }
    }
}

// ---------------------------------------------------------------------------
extern "C" void kernel_launch(void* const* d_in, const int* in_sizes, int n_in,
                              void* d_out, int out_size) {
    const float* X   = (const float*)d_in[0];  // [B,N,F]
    const int*   adj = (const int*)  d_in[1];  // [B,N,N]
    const float* Wf  = (const float*)d_in[2];  // [F,U]
    const float* bf  = (const float*)d_in[3];  // [U]
    const float* Ws  = (const float*)d_in[4];  // [2U]
    // d_in[5] = bs: constant along softmax axis -> cancels. w2 likewise unused.
    float* out = (float*)d_out;

    float *T, *e, *Wfr, *v, *b0;
    cudaGetSymbolAddress((void**)&T, g_T);
    cudaGetSymbolAddress((void**)&e, g_e);
    cudaGetSymbolAddress((void**)&Wfr, g_Wfr);
    cudaGetSymbolAddress((void**)&v, g_v);
    cudaGetSymbolAddress((void**)&b0, g_b0);

    cudaFuncSetAttribute(k_feat, cudaFuncAttributeMaxDynamicSharedMemorySize,
                         (int)FEAT_SMEM_BYTES);
    cudaFuncSetAttribute(k_attn, cudaFuncAttributeMaxDynamicSharedMemorySize,
                         (int)ATTN_SMEM_BYTES);

    k_wf<<<(FF * UU + 255) / 256, 256>>>(Wf, Wfr);
    k_wv<<<129, 128>>>(Wf, bf, Ws, v, b0);
    k_feat<<<128, 256, FEAT_SMEM_BYTES>>>(X, Wfr, bf, T);
    k_ae<<<2048, 256>>>(X, v, b0, e);
    dim3 grid(16, BB);
    k_attn<<<grid, 512, ATTN_SMEM_BYTES>>>(adj, T, e, out);
}